// round 16
// baseline (speedup 1.0000x reference)
#include <cuda_runtime.h>
#include <math.h>

#define NN    2048
#define TLEN  1000
#define T2    994
#define TP2   248
#define T3    242
#define TP3   60
#define C1    32
#define C2    64
#define C3    128
#define NE    32768
#define NB    32
#define EMB   768
#define FLAT  7680
#define EPS   1e-5f
#define HROW  164   // skewed h-tile row stride in floats (41 float4)

typedef unsigned long long u64;

__device__ __forceinline__ u64 pk(float lo, float hi) {
    u64 r; asm("mov.b64 %0, {%1, %2};" : "=l"(r) : "f"(lo), "f"(hi)); return r;
}
__device__ __forceinline__ void fma2(u64 &d, u64 a, u64 b) {
    asm("fma.rn.f32x2 %0, %1, %2, %0;" : "+l"(d) : "l"(a), "l"(b));
}
__device__ __forceinline__ float2 upk(u64 v) {
    float2 r; asm("mov.b64 {%0, %1}, %2;" : "=f"(r.x), "=f"(r.y) : "l"(v)); return r;
}

// ---------------- device scratch ----------------
__device__ float g_w2t[224 * C2];          // conv2 weights transposed [i*7+k][o]
__device__ float g_w3t[448 * C3];          // conv3 weights transposed [i*7+k][o]
__device__ float g_y2p[NN * C2 * TP2];
__device__ float g_y3p[NN * C3 * TP3];     // layout n*7680 + c*60 + w  (== GCN input order)
__device__ float g_pe[NN * C3];
__device__ float g_Z1[NN * EMB];
__device__ float g_H1[NN * EMB];
__device__ float g_Z2[NN * EMB];
__device__ float g_H2[NN * EMB];
__device__ float g_bn1_sum[C1], g_bn1_sq[C1];
__device__ float g_bn2_sum[C2], g_bn2_sq[C2];
__device__ float g_bn3_sum[C3], g_bn3_sq[C3];
__device__ float g_w1s[C1 * 7], g_c0[C1];
__device__ float g_s2[C2], g_t2[C2];
__device__ float g_s3[C3], g_t3[C3];
__device__ int   g_deg[NN], g_cursor[NN], g_off[NN + 1], g_csrc[NE];
__device__ float g_dinv[NN], g_invdeg[NN];

// ---------------- init + weight transposes ----------------
__global__ void k_init() {
    int i = blockIdx.x * 256 + threadIdx.x;
    if (i < NN)  { g_deg[i] = 0; g_cursor[i] = 0; }
    if (i < C1)  { g_bn1_sum[i] = 0.f; g_bn1_sq[i] = 0.f; }
    if (i < C2)  { g_bn2_sum[i] = 0.f; g_bn2_sq[i] = 0.f; }
    if (i < C3)  { g_bn3_sum[i] = 0.f; g_bn3_sq[i] = 0.f; }
}
__global__ void k_w2t(const float* __restrict__ w2) {
    int i = blockIdx.x * 256 + threadIdx.x;
    if (i < 224 * C2) { int r = i >> 6, o = i & 63; g_w2t[i] = w2[o * 224 + r]; }
}
__global__ void k_w3t(const float* __restrict__ w3) {
    int i = blockIdx.x * 256 + threadIdx.x;
    if (i < 448 * C3) { int r = i >> 7, o = i & 127; g_w3t[i] = w3[o * 448 + r]; }
}

// ---------------- bn1 stats straight from x ----------------
__global__ void __launch_bounds__(256) k_bn1stats(const float* __restrict__ x,
                                                  const float* __restrict__ w1,
                                                  const float* __restrict__ b1) {
    __shared__ float xs[TLEN + 6];
    __shared__ float rs[256], rq[256];
    int n = blockIdx.x, tid = threadIdx.x;
    for (int j = tid; j < TLEN + 6; j += 256) {
        int g = j - 3;
        xs[j] = (g >= 0 && g < TLEN) ? x[n * TLEN + g] : 0.f;
    }
    __syncthreads();
    int c = tid >> 3, s = tid & 7;
    float w[7];
    #pragma unroll
    for (int k = 0; k < 7; k++) w[k] = w1[c * 7 + k];
    float bb = b1[c];
    float sum = 0.f, sq = 0.f;
    for (int t = s; t < TLEN; t += 8) {
        float v = bb;
        #pragma unroll
        for (int k = 0; k < 7; k++) v = fmaf(w[k], xs[t + k], v);
        sum += v; sq = fmaf(v, v, sq);
    }
    rs[tid] = sum; rq[tid] = sq;
    __syncthreads();
    for (int off = 4; off > 0; off >>= 1) {
        if (s < off) { rs[tid] += rs[tid + off]; rq[tid] += rq[tid + off]; }
        __syncthreads();
    }
    if (s == 0) {
        atomicAdd(&g_bn1_sum[c], rs[tid]);
        atomicAdd(&g_bn1_sq[c], rq[tid]);
    }
}

// ---------------- finalize BN scale/shift ----------------
__global__ void k_fin(int stage, const float* __restrict__ g, const float* __restrict__ bt,
                      const float* __restrict__ w1, const float* __restrict__ b1) {
    int c = threadIdx.x;
    if (stage == 0 && c < C1) {
        float cnt = (float)NN * (float)TLEN;
        float m = g_bn1_sum[c] / cnt;
        float v = g_bn1_sq[c] / cnt - m * m;
        float sc = g[c] * rsqrtf(v + EPS);
        float sh = bt[c] - m * sc;
        for (int k = 0; k < 7; k++) g_w1s[c * 7 + k] = sc * w1[c * 7 + k];
        g_c0[c] = sc * b1[c] + sh;
    } else if (stage == 1 && c < C2) {
        float cnt = (float)NN * (float)T2;
        float m = g_bn2_sum[c] / cnt;
        float v = g_bn2_sq[c] / cnt - m * m;
        float sc = g[c] * rsqrtf(v + EPS);
        g_s2[c] = sc; g_t2[c] = bt[c] - m * sc;
    } else if (stage == 2 && c < C3) {
        float cnt = (float)NN * (float)T3;
        float m = g_bn3_sum[c] / cnt;
        float v = g_bn3_sq[c] / cnt - m * m;
        float sc = g[c] * rsqrtf(v + EPS);
        g_s3[c] = sc; g_t3[c] = bt[c] - m * sc;
    }
}

// ---------------- conv2: 8t x 4o, o-width 64, skewed h, i-chunked weights ----
// grid (8 t-tiles, NN), 256 threads, dyn smem 51760 B, 3 CTAs/SM
__global__ void __launch_bounds__(256, 3) k_conv2(const float* __restrict__ x,
                                                  const float* __restrict__ b2) {
    extern __shared__ float sm[];
    float* xs   = sm;                 // 140
    float* h1s  = sm + 140;           // 32*164 = 5248 (skewed)
    float* wsm  = h1s + 5248;         // 112 rows * 64 o = 7168
    float* w1sm = wsm + 7168;         // 224
    float* c0sm = w1sm + 224;         // 32
    float* ssum = c0sm + 32;          // 64
    float* ssq  = ssum + 64;          // 64
    int tid = threadIdx.x;
    int t0 = blockIdx.x * 128, n = blockIdx.y;

    if (tid < 224) w1sm[tid] = g_w1s[tid];
    if (tid < C1)  c0sm[tid] = g_c0[tid];
    if (tid < C2)  { ssum[tid] = 0.f; ssq[tid] = 0.f; }
    if (tid < 140) {
        int g = t0 + tid - 3;
        xs[tid] = (g >= 0 && g < TLEN) ? x[n * TLEN + g] : 0.f;
    }
    __syncthreads();

    {   // recompute conv1 + bn1 + relu into skewed h1s
        int i = tid >> 3, s = tid & 7;
        float w[7];
        #pragma unroll
        for (int k = 0; k < 7; k++) w[k] = w1sm[i * 7 + k];
        float c0v = c0sm[i];
        for (int j = s; j < 134; j += 8) {
            float v = c0v;
            #pragma unroll
            for (int k = 0; k < 7; k++) v = fmaf(w[k], xs[j + k], v);
            h1s[i * HROW + j + ((j >> 5) << 2)] = fmaxf(v, 0.f);
        }
    }

    int tIdx = tid & 15, oIdx = tid >> 4;
    int tb = tIdx * 8, ob = oIdx * 4;
    int p0, p1, p2, p3;
    {
        int c = 2 * tIdx;
        p0 = c + (c >> 3); c++;
        p1 = c + (c >> 3); c++;
        p2 = c + (c >> 3); c++;
        p3 = c + (c >> 3);
    }
    u64 acc2[2][8];
    {
        u64 b01 = pk(b2[ob], b2[ob + 1]);
        u64 b23 = pk(b2[ob + 2], b2[ob + 3]);
        #pragma unroll
        for (int t = 0; t < 8; t++) { acc2[0][t] = b01; acc2[1][t] = b23; }
    }

    for (int ic = 0; ic < 2; ic++) {
        __syncthreads();
        for (int idx = tid; idx < 112 * C2; idx += 256)
            wsm[idx] = g_w2t[ic * 112 * C2 + idx];
        __syncthreads();
        for (int il = 0; il < 16; il++) {
            int i = ic * 16 + il;
            float hr[16];
            const float4* hrow = (const float4*)(h1s + i * HROW);
            *(float4*)(hr)      = hrow[p0];
            *(float4*)(hr + 4)  = hrow[p1];
            *(float4*)(hr + 8)  = hrow[p2];
            *(float4*)(hr + 12) = hrow[p3];
            u64 hb[14];
            #pragma unroll
            for (int j = 0; j < 14; j++) hb[j] = pk(hr[j], hr[j]);
            const float* wrow = wsm + il * 7 * C2 + ob;
            #pragma unroll
            for (int k = 0; k < 7; k++) {
                ulonglong2 wv = *(const ulonglong2*)(wrow + k * C2);
                #pragma unroll
                for (int t = 0; t < 8; t++) {
                    fma2(acc2[0][t], hb[t + k], wv.x);
                    fma2(acc2[1][t], hb[t + k], wv.y);
                }
            }
        }
    }

    float accf[4][8];
    #pragma unroll
    for (int t = 0; t < 8; t++) {
        float2 v0 = upk(acc2[0][t]); accf[0][t] = v0.x; accf[1][t] = v0.y;
        float2 v1 = upk(acc2[1][t]); accf[2][t] = v1.x; accf[3][t] = v1.y;
    }

    int validT = min(128, T2 - t0);
    #pragma unroll
    for (int oo = 0; oo < 4; oo++) {
        float s = 0.f, q = 0.f;
        #pragma unroll
        for (int t = 0; t < 8; t++) {
            if (tb + t < validT) { float v = accf[oo][t]; s += v; q = fmaf(v, v, q); }
        }
        atomicAdd(&ssum[ob + oo], s);
        atomicAdd(&ssq[ob + oo], q);
        #pragma unroll
        for (int p = 0; p < 2; p++) {
            int w = (t0 + tb) / 4 + p;
            if (w < TP2) {
                float pv = 0.25f * (accf[oo][4*p] + accf[oo][4*p+1] + accf[oo][4*p+2] + accf[oo][4*p+3]);
                g_y2p[(n * C2 + ob + oo) * TP2 + w] = pv;
            }
        }
    }
    __syncthreads();
    if (tid < C2) {
        atomicAdd(&g_bn2_sum[tid], ssum[tid]);
        atomicAdd(&g_bn2_sq[tid], ssq[tid]);
    }
}

// ---------------- conv3: 8t x 4o, o-split 32, skewed h, i-chunked weights ----
// grid (2 t-tiles * 4 o-quarters, NN), 128 threads, dyn smem 71424 B, 3 CTAs/SM
__global__ void __launch_bounds__(128, 3) k_conv3(const float* __restrict__ b3) {
    extern __shared__ float sm[];
    float* h2s  = sm;                 // 64*164 = 10496 (skewed)
    float* wsm  = sm + 10496;         // 224 rows * 32 o = 7168
    float* ss2  = wsm + 7168;         // 64
    float* tt2  = ss2 + 64;           // 64
    float* ssum = tt2 + 64;           // 32
    float* ssq  = ssum + 32;          // 32
    int tid = threadIdx.x;
    int bx  = blockIdx.x;
    int t0  = (bx & 1) * 128;
    int oh  = (bx >> 1) * 32;
    int n   = blockIdx.y;

    if (tid < C2) { ss2[tid] = g_s2[tid]; tt2[tid] = g_t2[tid]; }
    if (tid < 32) { ssum[tid] = 0.f; ssq[tid] = 0.f; }
    __syncthreads();

    for (int idx = tid; idx < C2 * 134; idx += 128) {
        int i = idx / 134, j = idx - i * 134;
        int g = t0 + j;
        float v = (g < TP2) ? g_y2p[(n * C2 + i) * TP2 + g] : 0.f;
        h2s[i * HROW + j + ((j >> 5) << 2)] = fmaxf(fmaf(v, ss2[i], tt2[i]), 0.f);
    }

    int tIdx = tid & 15, oIdx = tid >> 4;
    int tb = tIdx * 8, ob = oIdx * 4;
    int p0, p1, p2, p3;
    {
        int c = 2 * tIdx;
        p0 = c + (c >> 3); c++;
        p1 = c + (c >> 3); c++;
        p2 = c + (c >> 3); c++;
        p3 = c + (c >> 3);
    }
    u64 acc2[2][8];
    {
        u64 b01 = pk(b3[oh + ob], b3[oh + ob + 1]);
        u64 b23 = pk(b3[oh + ob + 2], b3[oh + ob + 3]);
        #pragma unroll
        for (int t = 0; t < 8; t++) { acc2[0][t] = b01; acc2[1][t] = b23; }
    }

    for (int ic = 0; ic < 2; ic++) {
        __syncthreads();
        for (int idx = tid; idx < 224 * 32; idx += 128) {
            int r = idx >> 5, ol = idx & 31;
            wsm[idx] = g_w3t[(ic * 224 + r) * C3 + oh + ol];
        }
        __syncthreads();
        for (int il = 0; il < 32; il++) {
            int i = ic * 32 + il;
            float hr[16];
            const float4* hrow = (const float4*)(h2s + i * HROW);
            *(float4*)(hr)      = hrow[p0];
            *(float4*)(hr + 4)  = hrow[p1];
            *(float4*)(hr + 8)  = hrow[p2];
            *(float4*)(hr + 12) = hrow[p3];
            u64 hb[14];
            #pragma unroll
            for (int j = 0; j < 14; j++) hb[j] = pk(hr[j], hr[j]);
            const float* wrow = wsm + il * 7 * 32 + ob;
            #pragma unroll
            for (int k = 0; k < 7; k++) {
                ulonglong2 wv = *(const ulonglong2*)(wrow + k * 32);
                #pragma unroll
                for (int t = 0; t < 8; t++) {
                    fma2(acc2[0][t], hb[t + k], wv.x);
                    fma2(acc2[1][t], hb[t + k], wv.y);
                }
            }
        }
    }

    float accf[4][8];
    #pragma unroll
    for (int t = 0; t < 8; t++) {
        float2 v0 = upk(acc2[0][t]); accf[0][t] = v0.x; accf[1][t] = v0.y;
        float2 v1 = upk(acc2[1][t]); accf[2][t] = v1.x; accf[3][t] = v1.y;
    }

    int validT = min(128, T3 - t0);
    #pragma unroll
    for (int oo = 0; oo < 4; oo++) {
        float s = 0.f, q = 0.f;
        #pragma unroll
        for (int t = 0; t < 8; t++) {
            if (tb + t < validT) { float v = accf[oo][t]; s += v; q = fmaf(v, v, q); }
        }
        atomicAdd(&ssum[ob + oo], s);
        atomicAdd(&ssq[ob + oo], q);
        #pragma unroll
        for (int p = 0; p < 2; p++) {
            int w = (t0 + tb) / 4 + p;
            if (w < TP3) {
                float pv = 0.25f * (accf[oo][4*p] + accf[oo][4*p+1] + accf[oo][4*p+2] + accf[oo][4*p+3]);
                g_y3p[(n * C3 + oh + ob + oo) * TP3 + w] = pv;
            }
        }
    }
    __syncthreads();
    if (tid < 32) {
        atomicAdd(&g_bn3_sum[oh + tid], ssum[tid]);
        atomicAdd(&g_bn3_sq[oh + tid], ssq[tid]);
    }
}

// ---------------- positional MLP ----------------
__global__ void k_pe(const float* __restrict__ pos,
                     const float* __restrict__ w1, const float* __restrict__ b1,
                     const float* __restrict__ w2, const float* __restrict__ b2) {
    __shared__ float hs[C3];
    int n = blockIdx.x, j = threadIdx.x;
    float p0 = pos[n * 3], p1 = pos[n * 3 + 1], p2 = pos[n * 3 + 2];
    float h = b1[j] + p0 * w1[j] + p1 * w1[C3 + j] + p2 * w1[2 * C3 + j];
    hs[j] = fmaxf(h, 0.f);
    __syncthreads();
    float acc = b2[j];
    for (int i = 0; i < C3; i++) acc = fmaf(hs[i], w2[i * C3 + j], acc);
    g_pe[n * C3 + j] = acc;
}

// ---------------- graph prep ----------------
__global__ void k_deg(const int* __restrict__ dst) {
    int e = blockIdx.x * 256 + threadIdx.x;
    if (e < NE) atomicAdd(&g_deg[dst[e]], 1);
}
__global__ void k_nodeprep() {
    int i = blockIdx.x * 256 + threadIdx.x;
    if (i < NN) {
        float d = (float)(g_deg[i] + 1);
        g_dinv[i]   = rsqrtf(d);
        g_invdeg[i] = 1.0f / d;
    }
}
__global__ void k_scan() {
    __shared__ int part[256];
    int tid = threadIdx.x;
    int base = tid * 8;
    int loc[8]; int s = 0;
    #pragma unroll
    for (int j = 0; j < 8; j++) { loc[j] = g_deg[base + j]; s += loc[j]; }
    part[tid] = s;
    __syncthreads();
    if (tid == 0) {
        int run = 0;
        for (int i = 0; i < 256; i++) { int t = part[i]; part[i] = run; run += t; }
    }
    __syncthreads();
    int run = part[tid];
    #pragma unroll
    for (int j = 0; j < 8; j++) { g_off[base + j] = run; run += loc[j]; }
    if (tid == 255) g_off[NN] = run;
}
__global__ void k_fill(const int* __restrict__ src, const int* __restrict__ dst) {
    int e = blockIdx.x * 256 + threadIdx.x;
    if (e < NE) {
        int d = dst[e];
        int p = atomicAdd(&g_cursor[d], 1);
        g_csrc[g_off[d] + p] = src[e];
    }
}

// ---------------- GEMM: C[2048,Nd] = A[2048,Kd] @ W[Kd,Nd], 128x64, f32x2 ----
// which==0: A = relu(bn3(y3p)) + pe  (fused, Kd=7680)   which==1: A = g_H1 (Kd=768)
__global__ void __launch_bounds__(256) k_gemm(int which, const float* __restrict__ W,
                                              int Kd, int Nd) {
    __shared__ float As[128 * 32];   // [m][k] 16 KB
    __shared__ float Bs[32 * 64];    // [k][n]  8 KB
    float* C = (which == 0) ? g_Z1 : g_Z2;
    int tid = threadIdx.x;
    int n0 = blockIdx.x * 64, m0 = blockIdx.y * 128;
    int tx = tid & 15, ty = tid >> 4;          // 16 n-groups x 16 m-groups
    u64 acc2[8][2];
    #pragma unroll
    for (int j = 0; j < 8; j++) { acc2[j][0] = 0ull; acc2[j][1] = 0ull; }

    for (int k0 = 0; k0 < Kd; k0 += 32) {
        #pragma unroll
        for (int l = 0; l < 4; l++) {
            int idx4 = tid + l * 256;          // 0..1023
            int m = idx4 >> 3;                 // 0..127
            int c4 = (idx4 & 7) * 4;           // 0..28
            int node = m0 + m;
            if (which == 0) {
                int col = k0 + c4;
                float4 v = *(const float4*)(g_y3p + (long long)node * FLAT + col);
                float r[4] = {v.x, v.y, v.z, v.w};
                #pragma unroll
                for (int e = 0; e < 4; e++) {
                    int cc = (col + e) / TP3;
                    r[e] = fmaxf(fmaf(r[e], g_s3[cc], g_t3[cc]), 0.f) + g_pe[node * C3 + cc];
                }
                float4 o; o.x = r[0]; o.y = r[1]; o.z = r[2]; o.w = r[3];
                *(float4*)(As + m * 32 + c4) = o;
            } else {
                *(float4*)(As + m * 32 + c4) =
                    *(const float4*)(g_H1 + (long long)node * EMB + k0 + c4);
            }
        }
        #pragma unroll
        for (int l = 0; l < 2; l++) {
            int idx4 = tid + l * 256;          // 0..511
            int kk = idx4 >> 4;                // 0..31
            int nc4 = (idx4 & 15) * 4;         // 0..60
            *(float4*)(Bs + kk * 64 + nc4) =
                *(const float4*)(W + (long long)(k0 + kk) * Nd + n0 + nc4);
        }
        __syncthreads();
        #pragma unroll
        for (int k = 0; k < 32; k++) {
            ulonglong2 bv = *(const ulonglong2*)(Bs + k * 64 + tx * 4);
            #pragma unroll
            for (int j = 0; j < 8; j++) {
                float a = As[(ty * 8 + j) * 32 + k];
                u64 pa = pk(a, a);
                fma2(acc2[j][0], pa, bv.x);
                fma2(acc2[j][1], pa, bv.y);
            }
        }
        __syncthreads();
    }
    #pragma unroll
    for (int j = 0; j < 8; j++) {
        float2 lo = upk(acc2[j][0]), hi = upk(acc2[j][1]);
        float4 o; o.x = lo.x; o.y = lo.y; o.z = hi.x; o.w = hi.y;
        *(float4*)(C + (long long)(m0 + ty * 8 + j) * Nd + n0 + tx * 4) = o;
    }
}

// ---------------- GCN aggregation: relu(agg + Z*invdeg + b) ----------------
__global__ void __launch_bounds__(256) k_agg(int which, const float* __restrict__ bias) {
    __shared__ int   ssrc[256];
    __shared__ float scoef[256];
    const float* Z = (which == 0) ? g_Z1 : g_Z2;
    float* H       = (which == 0) ? g_H1 : g_H2;
    int d = blockIdx.x, tid = threadIdx.x;
    int e0 = g_off[d], e1 = g_off[d + 1];
    float dv = g_dinv[d], iv = g_invdeg[d];
    float acc[3];
    #pragma unroll
    for (int j = 0; j < 3; j++) acc[j] = Z[d * EMB + tid + 256 * j] * iv;
    for (int ec = e0; ec < e1; ec += 256) {
        int cnt = min(256, e1 - ec);
        __syncthreads();
        if (tid < cnt) {
            int s = g_csrc[ec + tid];
            ssrc[tid] = s;
            scoef[tid] = g_dinv[s] * dv;
        }
        __syncthreads();
        for (int e = 0; e < cnt; e++) {
            int s = ssrc[e]; float cf = scoef[e];
            #pragma unroll
            for (int j = 0; j < 3; j++)
                acc[j] = fmaf(Z[s * EMB + tid + 256 * j], cf, acc[j]);
        }
    }
    #pragma unroll
    for (int j = 0; j < 3; j++) {
        int f = tid + 256 * j;
        H[d * EMB + f] = fmaxf(acc[j] + bias[f], 0.f);
    }
}

// ---------------- mean-pool + dense + log_softmax ----------------
__global__ void k_head(const float* __restrict__ dw, const float* __restrict__ db,
                       float* __restrict__ out) {
    __shared__ float pooled[EMB];
    __shared__ float red[256];
    __shared__ float logits[4];
    int b = blockIdx.x, tid = threadIdx.x;
    for (int f = tid; f < EMB; f += 256) {
        float s = 0.f;
        for (int n = b * 64; n < b * 64 + 64; n++) s += g_H2[n * EMB + f];
        pooled[f] = s * (1.f / 64.f);
    }
    __syncthreads();
    for (int c = 0; c < 4; c++) {
        float p = 0.f;
        for (int f = tid; f < EMB; f += 256) p = fmaf(pooled[f], dw[f * 4 + c], p);
        red[tid] = p;
        __syncthreads();
        for (int off = 128; off > 0; off >>= 1) {
            if (tid < off) red[tid] += red[tid + off];
            __syncthreads();
        }
        if (tid == 0) logits[c] = red[0] + db[c];
        __syncthreads();
    }
    if (tid == 0) {
        float m = logits[0];
        for (int c = 1; c < 4; c++) m = fmaxf(m, logits[c]);
        float s = 0.f;
        for (int c = 0; c < 4; c++) s += expf(logits[c] - m);
        float lse = logf(s);
        for (int c = 0; c < 4; c++) out[b * 4 + c] = logits[c] - m - lse;
    }
}

// ---------------- launch ----------------
extern "C" void kernel_launch(void* const* d_in, const int* in_sizes, int n_in,
                              void* d_out, int out_size) {
    const float* x       = (const float*)d_in[0];
    const float* pos     = (const float*)d_in[1];
    const int*   ei      = (const int*)d_in[2];
    const float* conv1_w = (const float*)d_in[4];
    const float* conv1_b = (const float*)d_in[5];
    const float* bn1_g   = (const float*)d_in[6];
    const float* bn1_b   = (const float*)d_in[7];
    const float* conv2_w = (const float*)d_in[8];
    const float* conv2_b = (const float*)d_in[9];
    const float* bn2_g   = (const float*)d_in[10];
    const float* bn2_b   = (const float*)d_in[11];
    const float* conv3_w = (const float*)d_in[12];
    const float* conv3_b = (const float*)d_in[13];
    const float* bn3_g   = (const float*)d_in[14];
    const float* bn3_b   = (const float*)d_in[15];
    const float* pos_w1  = (const float*)d_in[16];
    const float* pos_b1  = (const float*)d_in[17];
    const float* pos_w2  = (const float*)d_in[18];
    const float* pos_b2  = (const float*)d_in[19];
    const float* gcn1_w  = (const float*)d_in[20];
    const float* gcn1_b  = (const float*)d_in[21];
    const float* gcn2_w  = (const float*)d_in[22];
    const float* gcn2_b  = (const float*)d_in[23];
    const float* dense_w = (const float*)d_in[24];
    const float* dense_b = (const float*)d_in[25];
    const int* src = ei;
    const int* dst = ei + NE;
    float* out = (float*)d_out;

    cudaFuncSetAttribute(k_conv2, cudaFuncAttributeMaxDynamicSharedMemorySize, 51760);
    cudaFuncSetAttribute(k_conv3, cudaFuncAttributeMaxDynamicSharedMemorySize, 71424);

    k_init<<<8, 256>>>();
    k_w2t<<<(224 * C2 + 255) / 256, 256>>>(conv2_w);
    k_w3t<<<(448 * C3 + 255) / 256, 256>>>(conv3_w);
    k_bn1stats<<<NN, 256>>>(x, conv1_w, conv1_b);
    k_fin<<<1, 128>>>(0, bn1_g, bn1_b, conv1_w, conv1_b);
    k_conv2<<<dim3(8, NN), 256, 51760>>>(x, conv2_b);
    k_fin<<<1, 128>>>(1, bn2_g, bn2_b, conv1_w, conv1_b);
    k_conv3<<<dim3(8, NN), 128, 71424>>>(conv3_b);
    k_fin<<<1, 128>>>(2, bn3_g, bn3_b, conv1_w, conv1_b);

    k_pe<<<NN, 128>>>(pos, pos_w1, pos_b1, pos_w2, pos_b2);
    k_gemm<<<dim3(EMB / 64, NN / 128), 256>>>(0, gcn1_w, FLAT, EMB);

    k_deg<<<NE / 256, 256>>>(dst);
    k_nodeprep<<<8, 256>>>();
    k_scan<<<1, 256>>>();
    k_fill<<<NE / 256, 256>>>(src, dst);

    k_agg<<<NN, 256>>>(0, gcn1_b);
    k_gemm<<<dim3(EMB / 64, NN / 128), 256>>>(1, gcn2_w, EMB, EMB);
    k_agg<<<NN, 256>>>(1, gcn2_b);

    k_head<<<NB, 256>>>(dense_w, dense_b, out);
}

// round 17
// speedup vs baseline: 1.0982x; 1.0982x over previous
#include <cuda_runtime.h>
#include <math.h>

#define NN    2048
#define TLEN  1000
#define T2    994
#define TP2   248
#define T3    242
#define TP3   60
#define C1    32
#define C2    64
#define C3    128
#define NE    32768
#define NB    32
#define EMB   768
#define FLAT  7680
#define EPS   1e-5f
#define HROW  164   // skewed h-tile row stride in floats (41 float4)

typedef unsigned long long u64;

__device__ __forceinline__ u64 pk(float lo, float hi) {
    u64 r; asm("mov.b64 %0, {%1, %2};" : "=l"(r) : "f"(lo), "f"(hi)); return r;
}
__device__ __forceinline__ void fma2(u64 &d, u64 a, u64 b) {
    asm("fma.rn.f32x2 %0, %1, %2, %0;" : "+l"(d) : "l"(a), "l"(b));
}
__device__ __forceinline__ float2 upk(u64 v) {
    float2 r; asm("mov.b64 {%0, %1}, %2;" : "=f"(r.x), "=f"(r.y) : "l"(v)); return r;
}

// ---------------- device scratch ----------------
__device__ float g_w2t[224 * C2];          // conv2 weights transposed [i*7+k][o]
__device__ float g_w3t[448 * C3];          // conv3 weights transposed [i*7+k][o]
__device__ float g_y2p[NN * C2 * TP2];
__device__ float g_y3p[NN * C3 * TP3];     // layout n*7680 + c*60 + w
__device__ float g_pe[NN * C3];
__device__ float g_Z1[NN * EMB];
__device__ float g_H1[NN * EMB];
__device__ float g_Z2[NN * EMB];
__device__ float g_H2[NN * EMB];
__device__ float g_bn1_sum[C1], g_bn1_sq[C1];
__device__ float g_bn2_sum[C2], g_bn2_sq[C2];
__device__ float g_bn3_sum[C3], g_bn3_sq[C3];
__device__ float g_w1s[C1 * 7], g_c0[C1];
__device__ float g_s2[C2], g_t2[C2];
__device__ float g_s3[C3], g_t3[C3];
__device__ int   g_deg[NN], g_cursor[NN], g_off[NN + 1], g_csrc[NE];
__device__ float g_dinv[NN], g_invdeg[NN];

// ---------------- merged prep: init + both weight transposes (launch #1) ----
__global__ void k_prep(const float* __restrict__ w2, const float* __restrict__ w3) {
    int i = blockIdx.x * 256 + threadIdx.x;
    if (i < NN)  { g_deg[i] = 0; g_cursor[i] = 0; }
    if (i < C1)  { g_bn1_sum[i] = 0.f; g_bn1_sq[i] = 0.f; }
    if (i < C2)  { g_bn2_sum[i] = 0.f; g_bn2_sq[i] = 0.f; }
    if (i < C3)  { g_bn3_sum[i] = 0.f; g_bn3_sq[i] = 0.f; }
    if (i < 224 * C2) { int r = i >> 6, o = i & 63;  g_w2t[i] = w2[o * 224 + r]; }
    if (i < 448 * C3) { int r = i >> 7, o = i & 127; g_w3t[i] = w3[o * 448 + r]; }
}

// ---------------- bn1 stats straight from x (launch #2) ----------------
__global__ void __launch_bounds__(256) k_bn1stats(const float* __restrict__ x,
                                                  const float* __restrict__ w1,
                                                  const float* __restrict__ b1) {
    __shared__ float xs[TLEN + 6];
    __shared__ float rs[256], rq[256];
    int n = blockIdx.x, tid = threadIdx.x;
    for (int j = tid; j < TLEN + 6; j += 256) {
        int g = j - 3;
        xs[j] = (g >= 0 && g < TLEN) ? x[n * TLEN + g] : 0.f;
    }
    __syncthreads();
    int c = tid >> 3, s = tid & 7;
    float w[7];
    #pragma unroll
    for (int k = 0; k < 7; k++) w[k] = w1[c * 7 + k];
    float bb = b1[c];
    float sum = 0.f, sq = 0.f;
    for (int t = s; t < TLEN; t += 8) {
        float v = bb;
        #pragma unroll
        for (int k = 0; k < 7; k++) v = fmaf(w[k], xs[t + k], v);
        sum += v; sq = fmaf(v, v, sq);
    }
    rs[tid] = sum; rq[tid] = sq;
    __syncthreads();
    for (int off = 4; off > 0; off >>= 1) {
        if (s < off) { rs[tid] += rs[tid + off]; rq[tid] += rq[tid + off]; }
        __syncthreads();
    }
    if (s == 0) {
        atomicAdd(&g_bn1_sum[c], rs[tid]);
        atomicAdd(&g_bn1_sq[c], rq[tid]);
    }
}

// ---------------- finalize BN scale/shift ----------------
__global__ void k_fin(int stage, const float* __restrict__ g, const float* __restrict__ bt,
                      const float* __restrict__ w1, const float* __restrict__ b1) {
    int c = threadIdx.x;
    if (stage == 0 && c < C1) {
        float cnt = (float)NN * (float)TLEN;
        float m = g_bn1_sum[c] / cnt;
        float v = g_bn1_sq[c] / cnt - m * m;
        float sc = g[c] * rsqrtf(v + EPS);
        float sh = bt[c] - m * sc;
        for (int k = 0; k < 7; k++) g_w1s[c * 7 + k] = sc * w1[c * 7 + k];
        g_c0[c] = sc * b1[c] + sh;
    } else if (stage == 1 && c < C2) {
        float cnt = (float)NN * (float)T2;
        float m = g_bn2_sum[c] / cnt;
        float v = g_bn2_sq[c] / cnt - m * m;
        float sc = g[c] * rsqrtf(v + EPS);
        g_s2[c] = sc; g_t2[c] = bt[c] - m * sc;
    } else if (stage == 2 && c < C3) {
        float cnt = (float)NN * (float)T3;
        float m = g_bn3_sum[c] / cnt;
        float v = g_bn3_sq[c] / cnt - m * m;
        float sc = g[c] * rsqrtf(v + EPS);
        g_s3[c] = sc; g_t3[c] = bt[c] - m * sc;
    }
}

// ---------------- conv2: 8t x 4o, o-width 64, skewed h, i-chunked weights ----
// grid (8 t-tiles, NN), 256 threads, dyn smem 51760 B, 3 CTAs/SM  (launch #4)
__global__ void __launch_bounds__(256, 3) k_conv2(const float* __restrict__ x,
                                                  const float* __restrict__ b2) {
    extern __shared__ float sm[];
    float* xs   = sm;                 // 140
    float* h1s  = sm + 140;           // 32*164 = 5248 (skewed)
    float* wsm  = h1s + 5248;         // 112 rows * 64 o = 7168
    float* w1sm = wsm + 7168;         // 224
    float* c0sm = w1sm + 224;         // 32
    float* ssum = c0sm + 32;          // 64
    float* ssq  = ssum + 64;          // 64
    int tid = threadIdx.x;
    int t0 = blockIdx.x * 128, n = blockIdx.y;

    if (tid < 224) w1sm[tid] = g_w1s[tid];
    if (tid < C1)  c0sm[tid] = g_c0[tid];
    if (tid < C2)  { ssum[tid] = 0.f; ssq[tid] = 0.f; }
    if (tid < 140) {
        int g = t0 + tid - 3;
        xs[tid] = (g >= 0 && g < TLEN) ? x[n * TLEN + g] : 0.f;
    }
    __syncthreads();

    {   // recompute conv1 + bn1 + relu into skewed h1s
        int i = tid >> 3, s = tid & 7;
        float w[7];
        #pragma unroll
        for (int k = 0; k < 7; k++) w[k] = w1sm[i * 7 + k];
        float c0v = c0sm[i];
        for (int j = s; j < 134; j += 8) {
            float v = c0v;
            #pragma unroll
            for (int k = 0; k < 7; k++) v = fmaf(w[k], xs[j + k], v);
            h1s[i * HROW + j + ((j >> 5) << 2)] = fmaxf(v, 0.f);
        }
    }

    int tIdx = tid & 15, oIdx = tid >> 4;
    int tb = tIdx * 8, ob = oIdx * 4;
    int p0, p1, p2, p3;
    {
        int c = 2 * tIdx;
        p0 = c + (c >> 3); c++;
        p1 = c + (c >> 3); c++;
        p2 = c + (c >> 3); c++;
        p3 = c + (c >> 3);
    }
    u64 acc2[2][8];
    {
        u64 b01 = pk(b2[ob], b2[ob + 1]);
        u64 b23 = pk(b2[ob + 2], b2[ob + 3]);
        #pragma unroll
        for (int t = 0; t < 8; t++) { acc2[0][t] = b01; acc2[1][t] = b23; }
    }

    for (int ic = 0; ic < 2; ic++) {
        __syncthreads();
        for (int idx = tid; idx < 112 * C2; idx += 256)
            wsm[idx] = g_w2t[ic * 112 * C2 + idx];
        __syncthreads();
        for (int il = 0; il < 16; il++) {
            int i = ic * 16 + il;
            float hr[16];
            const float4* hrow = (const float4*)(h1s + i * HROW);
            *(float4*)(hr)      = hrow[p0];
            *(float4*)(hr + 4)  = hrow[p1];
            *(float4*)(hr + 8)  = hrow[p2];
            *(float4*)(hr + 12) = hrow[p3];
            u64 hb[14];
            #pragma unroll
            for (int j = 0; j < 14; j++) hb[j] = pk(hr[j], hr[j]);
            const float* wrow = wsm + il * 7 * C2 + ob;
            #pragma unroll
            for (int k = 0; k < 7; k++) {
                ulonglong2 wv = *(const ulonglong2*)(wrow + k * C2);
                #pragma unroll
                for (int t = 0; t < 8; t++) {
                    fma2(acc2[0][t], hb[t + k], wv.x);
                    fma2(acc2[1][t], hb[t + k], wv.y);
                }
            }
        }
    }

    float accf[4][8];
    #pragma unroll
    for (int t = 0; t < 8; t++) {
        float2 v0 = upk(acc2[0][t]); accf[0][t] = v0.x; accf[1][t] = v0.y;
        float2 v1 = upk(acc2[1][t]); accf[2][t] = v1.x; accf[3][t] = v1.y;
    }

    int validT = min(128, T2 - t0);
    #pragma unroll
    for (int oo = 0; oo < 4; oo++) {
        float s = 0.f, q = 0.f;
        #pragma unroll
        for (int t = 0; t < 8; t++) {
            if (tb + t < validT) { float v = accf[oo][t]; s += v; q = fmaf(v, v, q); }
        }
        atomicAdd(&ssum[ob + oo], s);
        atomicAdd(&ssq[ob + oo], q);
        #pragma unroll
        for (int p = 0; p < 2; p++) {
            int w = (t0 + tb) / 4 + p;
            if (w < TP2) {
                float pv = 0.25f * (accf[oo][4*p] + accf[oo][4*p+1] + accf[oo][4*p+2] + accf[oo][4*p+3]);
                g_y2p[(n * C2 + ob + oo) * TP2 + w] = pv;
            }
        }
    }
    __syncthreads();
    if (tid < C2) {
        atomicAdd(&g_bn2_sum[tid], ssum[tid]);
        atomicAdd(&g_bn2_sq[tid], ssq[tid]);
    }
}

// ---------------- conv3: 256 threads, 8t x 4o, o-width 64, 4-chunk weights ---
// grid (2 t-tiles * 2 o-halves, NN), 256 threads, dyn smem 71680 B, 3 CTAs/SM
__global__ void __launch_bounds__(256, 3) k_conv3(const float* __restrict__ b3) {
    extern __shared__ float sm[];
    float* h2s  = sm;                 // 64*164 = 10496 (skewed)
    float* wsm  = sm + 10496;         // 112 rows * 64 o = 7168 (chunk buffer)
    float* ss2  = wsm + 7168;         // 64
    float* tt2  = ss2 + 64;           // 64
    float* ssum = tt2 + 64;           // 64
    float* ssq  = ssum + 64;          // 64
    int tid = threadIdx.x;
    int bx  = blockIdx.x;
    int t0  = (bx & 1) * 128;
    int oh  = (bx >> 1) * 64;
    int n   = blockIdx.y;

    if (tid < C2) { ss2[tid] = g_s2[tid]; tt2[tid] = g_t2[tid]; }
    if (tid < 64) { ssum[tid] = 0.f; ssq[tid] = 0.f; }
    __syncthreads();

    for (int idx = tid; idx < C2 * 134; idx += 256) {
        int i = idx / 134, j = idx - i * 134;
        int g = t0 + j;
        float v = (g < TP2) ? g_y2p[(n * C2 + i) * TP2 + g] : 0.f;
        h2s[i * HROW + j + ((j >> 5) << 2)] = fmaxf(fmaf(v, ss2[i], tt2[i]), 0.f);
    }

    int tIdx = tid & 15, oIdx = tid >> 4;      // 16 t-groups x 16 o-groups
    int tb = tIdx * 8, ob = oIdx * 4;          // ob local in [0,64)
    int p0, p1, p2, p3;
    {
        int c = 2 * tIdx;
        p0 = c + (c >> 3); c++;
        p1 = c + (c >> 3); c++;
        p2 = c + (c >> 3); c++;
        p3 = c + (c >> 3);
    }
    u64 acc2[2][8];
    {
        u64 b01 = pk(b3[oh + ob], b3[oh + ob + 1]);
        u64 b23 = pk(b3[oh + ob + 2], b3[oh + ob + 3]);
        #pragma unroll
        for (int t = 0; t < 8; t++) { acc2[0][t] = b01; acc2[1][t] = b23; }
    }

    for (int ic = 0; ic < 4; ic++) {           // 4 chunks of 16 i (112 rows)
        __syncthreads();
        for (int idx = tid; idx < 112 * 64; idx += 256) {
            int r = idx >> 6, ol = idx & 63;
            wsm[idx] = g_w3t[(ic * 112 + r) * C3 + oh + ol];
        }
        __syncthreads();
        for (int il = 0; il < 16; il++) {
            int i = ic * 16 + il;
            float hr[16];
            const float4* hrow = (const float4*)(h2s + i * HROW);
            *(float4*)(hr)      = hrow[p0];
            *(float4*)(hr + 4)  = hrow[p1];
            *(float4*)(hr + 8)  = hrow[p2];
            *(float4*)(hr + 12) = hrow[p3];
            u64 hb[14];
            #pragma unroll
            for (int j = 0; j < 14; j++) hb[j] = pk(hr[j], hr[j]);
            const float* wrow = wsm + il * 7 * 64 + ob;
            #pragma unroll
            for (int k = 0; k < 7; k++) {
                ulonglong2 wv = *(const ulonglong2*)(wrow + k * 64);
                #pragma unroll
                for (int t = 0; t < 8; t++) {
                    fma2(acc2[0][t], hb[t + k], wv.x);
                    fma2(acc2[1][t], hb[t + k], wv.y);
                }
            }
        }
    }

    float accf[4][8];
    #pragma unroll
    for (int t = 0; t < 8; t++) {
        float2 v0 = upk(acc2[0][t]); accf[0][t] = v0.x; accf[1][t] = v0.y;
        float2 v1 = upk(acc2[1][t]); accf[2][t] = v1.x; accf[3][t] = v1.y;
    }

    int validT = min(128, T3 - t0);
    #pragma unroll
    for (int oo = 0; oo < 4; oo++) {
        float s = 0.f, q = 0.f;
        #pragma unroll
        for (int t = 0; t < 8; t++) {
            if (tb + t < validT) { float v = accf[oo][t]; s += v; q = fmaf(v, v, q); }
        }
        atomicAdd(&ssum[ob + oo], s);
        atomicAdd(&ssq[ob + oo], q);
        #pragma unroll
        for (int p = 0; p < 2; p++) {
            int w = (t0 + tb) / 4 + p;
            if (w < TP3) {
                float pv = 0.25f * (accf[oo][4*p] + accf[oo][4*p+1] + accf[oo][4*p+2] + accf[oo][4*p+3]);
                g_y3p[(n * C3 + oh + ob + oo) * TP3 + w] = pv;
            }
        }
    }
    __syncthreads();
    if (tid < 64) {
        atomicAdd(&g_bn3_sum[oh + tid], ssum[tid]);
        atomicAdd(&g_bn3_sq[oh + tid], ssq[tid]);
    }
}

// ---------------- positional MLP ----------------
__global__ void k_pe(const float* __restrict__ pos,
                     const float* __restrict__ w1, const float* __restrict__ b1,
                     const float* __restrict__ w2, const float* __restrict__ b2) {
    __shared__ float hs[C3];
    int n = blockIdx.x, j = threadIdx.x;
    float p0 = pos[n * 3], p1 = pos[n * 3 + 1], p2 = pos[n * 3 + 2];
    float h = b1[j] + p0 * w1[j] + p1 * w1[C3 + j] + p2 * w1[2 * C3 + j];
    hs[j] = fmaxf(h, 0.f);
    __syncthreads();
    float acc = b2[j];
    for (int i = 0; i < C3; i++) acc = fmaf(hs[i], w2[i * C3 + j], acc);
    g_pe[n * C3 + j] = acc;
}

// ---------------- graph prep ----------------
__global__ void k_deg(const int* __restrict__ dst) {
    int e = blockIdx.x * 256 + threadIdx.x;
    if (e < NE) atomicAdd(&g_deg[dst[e]], 1);
}
__global__ void k_nodeprep() {
    int i = blockIdx.x * 256 + threadIdx.x;
    if (i < NN) {
        float d = (float)(g_deg[i] + 1);
        g_dinv[i]   = rsqrtf(d);
        g_invdeg[i] = 1.0f / d;
    }
}
__global__ void k_scan() {
    __shared__ int part[256];
    int tid = threadIdx.x;
    int base = tid * 8;
    int loc[8]; int s = 0;
    #pragma unroll
    for (int j = 0; j < 8; j++) { loc[j] = g_deg[base + j]; s += loc[j]; }
    part[tid] = s;
    __syncthreads();
    if (tid == 0) {
        int run = 0;
        for (int i = 0; i < 256; i++) { int t = part[i]; part[i] = run; run += t; }
    }
    __syncthreads();
    int run = part[tid];
    #pragma unroll
    for (int j = 0; j < 8; j++) { g_off[base + j] = run; run += loc[j]; }
    if (tid == 255) g_off[NN] = run;
}
__global__ void k_fill(const int* __restrict__ src, const int* __restrict__ dst) {
    int e = blockIdx.x * 256 + threadIdx.x;
    if (e < NE) {
        int d = dst[e];
        int p = atomicAdd(&g_cursor[d], 1);
        g_csrc[g_off[d] + p] = src[e];
    }
}

// ---------------- GEMM: C[2048,Nd] = A[2048,Kd] @ W[Kd,Nd], 128x64, f32x2 ----
// which==0: A = relu(bn3(y3p)) + pe  (fused, Kd=7680)   which==1: A = g_H1 (Kd=768)
__global__ void __launch_bounds__(256) k_gemm(int which, const float* __restrict__ W,
                                              int Kd, int Nd) {
    __shared__ float As[128 * 32];   // [m][k] 16 KB
    __shared__ float Bs[32 * 64];    // [k][n]  8 KB
    float* C = (which == 0) ? g_Z1 : g_Z2;
    int tid = threadIdx.x;
    int n0 = blockIdx.x * 64, m0 = blockIdx.y * 128;
    int tx = tid & 15, ty = tid >> 4;
    u64 acc2[8][2];
    #pragma unroll
    for (int j = 0; j < 8; j++) { acc2[j][0] = 0ull; acc2[j][1] = 0ull; }

    for (int k0 = 0; k0 < Kd; k0 += 32) {
        #pragma unroll
        for (int l = 0; l < 4; l++) {
            int idx4 = tid + l * 256;
            int m = idx4 >> 3;
            int c4 = (idx4 & 7) * 4;
            int node = m0 + m;
            if (which == 0) {
                int col = k0 + c4;
                float4 v = *(const float4*)(g_y3p + (long long)node * FLAT + col);
                float r[4] = {v.x, v.y, v.z, v.w};
                #pragma unroll
                for (int e = 0; e < 4; e++) {
                    int cc = (col + e) / TP3;
                    r[e] = fmaxf(fmaf(r[e], g_s3[cc], g_t3[cc]), 0.f) + g_pe[node * C3 + cc];
                }
                float4 o; o.x = r[0]; o.y = r[1]; o.z = r[2]; o.w = r[3];
                *(float4*)(As + m * 32 + c4) = o;
            } else {
                *(float4*)(As + m * 32 + c4) =
                    *(const float4*)(g_H1 + (long long)node * EMB + k0 + c4);
            }
        }
        #pragma unroll
        for (int l = 0; l < 2; l++) {
            int idx4 = tid + l * 256;
            int kk = idx4 >> 4;
            int nc4 = (idx4 & 15) * 4;
            *(float4*)(Bs + kk * 64 + nc4) =
                *(const float4*)(W + (long long)(k0 + kk) * Nd + n0 + nc4);
        }
        __syncthreads();
        #pragma unroll
        for (int k = 0; k < 32; k++) {
            ulonglong2 bv = *(const ulonglong2*)(Bs + k * 64 + tx * 4);
            #pragma unroll
            for (int j = 0; j < 8; j++) {
                float a = As[(ty * 8 + j) * 32 + k];
                u64 pa = pk(a, a);
                fma2(acc2[j][0], pa, bv.x);
                fma2(acc2[j][1], pa, bv.y);
            }
        }
        __syncthreads();
    }
    #pragma unroll
    for (int j = 0; j < 8; j++) {
        float2 lo = upk(acc2[j][0]), hi = upk(acc2[j][1]);
        float4 o; o.x = lo.x; o.y = lo.y; o.z = hi.x; o.w = hi.y;
        *(float4*)(C + (long long)(m0 + ty * 8 + j) * Nd + n0 + tx * 4) = o;
    }
}

// ---------------- GCN aggregation: relu(agg + Z*invdeg + b) ----------------
__global__ void __launch_bounds__(256) k_agg(int which, const float* __restrict__ bias) {
    __shared__ int   ssrc[256];
    __shared__ float scoef[256];
    const float* Z = (which == 0) ? g_Z1 : g_Z2;
    float* H       = (which == 0) ? g_H1 : g_H2;
    int d = blockIdx.x, tid = threadIdx.x;
    int e0 = g_off[d], e1 = g_off[d + 1];
    float dv = g_dinv[d], iv = g_invdeg[d];
    float acc[3];
    #pragma unroll
    for (int j = 0; j < 3; j++) acc[j] = Z[d * EMB + tid + 256 * j] * iv;
    for (int ec = e0; ec < e1; ec += 256) {
        int cnt = min(256, e1 - ec);
        __syncthreads();
        if (tid < cnt) {
            int s = g_csrc[ec + tid];
            ssrc[tid] = s;
            scoef[tid] = g_dinv[s] * dv;
        }
        __syncthreads();
        for (int e = 0; e < cnt; e++) {
            int s = ssrc[e]; float cf = scoef[e];
            #pragma unroll
            for (int j = 0; j < 3; j++)
                acc[j] = fmaf(Z[s * EMB + tid + 256 * j], cf, acc[j]);
        }
    }
    #pragma unroll
    for (int j = 0; j < 3; j++) {
        int f = tid + 256 * j;
        H[d * EMB + f] = fmaxf(acc[j] + bias[f], 0.f);
    }
}

// ---------------- mean-pool + dense + log_softmax ----------------
__global__ void k_head(const float* __restrict__ dw, const float* __restrict__ db,
                       float* __restrict__ out) {
    __shared__ float pooled[EMB];
    __shared__ float red[256];
    __shared__ float logits[4];
    int b = blockIdx.x, tid = threadIdx.x;
    for (int f = tid; f < EMB; f += 256) {
        float s = 0.f;
        for (int n = b * 64; n < b * 64 + 64; n++) s += g_H2[n * EMB + f];
        pooled[f] = s * (1.f / 64.f);
    }
    __syncthreads();
    for (int c = 0; c < 4; c++) {
        float p = 0.f;
        for (int f = tid; f < EMB; f += 256) p = fmaf(pooled[f], dw[f * 4 + c], p);
        red[tid] = p;
        __syncthreads();
        for (int off = 128; off > 0; off >>= 1) {
            if (tid < off) red[tid] += red[tid + off];
            __syncthreads();
        }
        if (tid == 0) logits[c] = red[0] + db[c];
        __syncthreads();
    }
    if (tid == 0) {
        float m = logits[0];
        for (int c = 1; c < 4; c++) m = fmaxf(m, logits[c]);
        float s = 0.f;
        for (int c = 0; c < 4; c++) s += expf(logits[c] - m);
        float lse = logf(s);
        for (int c = 0; c < 4; c++) out[b * 4 + c] = logits[c] - m - lse;
    }
}

// ---------------- launch ----------------
extern "C" void kernel_launch(void* const* d_in, const int* in_sizes, int n_in,
                              void* d_out, int out_size) {
    const float* x       = (const float*)d_in[0];
    const float* pos     = (const float*)d_in[1];
    const int*   ei      = (const int*)d_in[2];
    const float* conv1_w = (const float*)d_in[4];
    const float* conv1_b = (const float*)d_in[5];
    const float* bn1_g   = (const float*)d_in[6];
    const float* bn1_b   = (const float*)d_in[7];
    const float* conv2_w = (const float*)d_in[8];
    const float* conv2_b = (const float*)d_in[9];
    const float* bn2_g   = (const float*)d_in[10];
    const float* bn2_b   = (const float*)d_in[11];
    const float* conv3_w = (const float*)d_in[12];
    const float* conv3_b = (const float*)d_in[13];
    const float* bn3_g   = (const float*)d_in[14];
    const float* bn3_b   = (const float*)d_in[15];
    const float* pos_w1  = (const float*)d_in[16];
    const float* pos_b1  = (const float*)d_in[17];
    const float* pos_w2  = (const float*)d_in[18];
    const float* pos_b2  = (const float*)d_in[19];
    const float* gcn1_w  = (const float*)d_in[20];
    const float* gcn1_b  = (const float*)d_in[21];
    const float* gcn2_w  = (const float*)d_in[22];
    const float* gcn2_b  = (const float*)d_in[23];
    const float* dense_w = (const float*)d_in[24];
    const float* dense_b = (const float*)d_in[25];
    const int* src = ei;
    const int* dst = ei + NE;
    float* out = (float*)d_out;

    cudaFuncSetAttribute(k_conv2, cudaFuncAttributeMaxDynamicSharedMemorySize, 51760);
    cudaFuncSetAttribute(k_conv3, cudaFuncAttributeMaxDynamicSharedMemorySize, 71680);

    // launch order: conv2 is the 4th launch (ncu samples the 4th)
    k_prep<<<224, 256>>>(conv2_w, conv3_w);
    k_bn1stats<<<NN, 256>>>(x, conv1_w, conv1_b);
    k_fin<<<1, 128>>>(0, bn1_g, bn1_b, conv1_w, conv1_b);
    k_conv2<<<dim3(8, NN), 256, 51760>>>(x, conv2_b);
    k_fin<<<1, 128>>>(1, bn2_g, bn2_b, conv1_w, conv1_b);
    k_conv3<<<dim3(4, NN), 256, 71680>>>(conv3_b);
    k_fin<<<1, 128>>>(2, bn3_g, bn3_b, conv1_w, conv1_b);

    k_pe<<<NN, 128>>>(pos, pos_w1, pos_b1, pos_w2, pos_b2);
    k_gemm<<<dim3(EMB / 64, NN / 128), 256>>>(0, gcn1_w, FLAT, EMB);

    k_deg<<<NE / 256, 256>>>(dst);
    k_nodeprep<<<8, 256>>>();
    k_scan<<<1, 256>>>();
    k_fill<<<NE / 256, 256>>>(src, dst);

    k_agg<<<NN, 256>>>(0, gcn1_b);
    k_gemm<<<dim3(EMB / 64, NN / 128), 256>>>(1, gcn2_w, EMB, EMB);
    k_agg<<<NN, 256>>>(1, gcn2_b);

    k_head<<<NB, 256>>>(dense_w, dense_b, out);
}